// round 17
// baseline (speedup 1.0000x reference)
#include <cuda_runtime.h>
#include <cuda_fp16.h>
#include <cstdint>

// Deformable Conv3d via portable HMMA — R17: 3 blocks/SM via register budget.
//   __launch_bounds__(256,3) (85 regs) + sampling corners processed in two
//   4-corner chunks (halves peak gather registers) so it fits without spills.
//   Otherwise identical to R16: half-warp-per-point sampling, fp16 single-term
//   MMA, fragment-ordered global B, per-warp-pair named barriers.

namespace {
constexpr int B_ = 2, CIN_ = 64, COUT_ = 64, D_ = 8, H_ = 32, W_ = 32, K_ = 27;
constexpr int P_ = D_ * H_ * W_;              // 8192
constexpr int MTILE = 64;
constexpr int THREADS = 256;
constexpr int NBLK = (B_ * P_) / MTILE;       // 256

constexpr int ABUF = 8192;                    // one A buffer (fp16, 64x128B)
constexpr int SM_TOTAL = 2 * ABUF;            // 16384
}

__device__ __align__(256) float g_xT[B_ * P_ * CIN_];   // channels-last x
// B fragments, uint4 units: [kt][jg(8)][kp(2)][lane(32)]
__device__ __align__(256) uint32_t g_wF[K_ * 8 * 2 * 32 * 4];

// ---------------- helpers ----------------
__device__ __forceinline__ uint32_t smem_u32(const void* p) {
    uint32_t a;
    asm("{ .reg .u64 t; cvta.to.shared.u64 t, %1; cvt.u32.u64 %0, t; }"
        : "=r"(a) : "l"(p));
    return a;
}
__device__ __forceinline__ uint32_t f16x2(float hi_elem, float lo_elem) {
    uint32_t r;
    asm("cvt.rn.f16x2.f32 %0, %1, %2;" : "=r"(r) : "f"(hi_elem), "f"(lo_elem));
    return r;
}
__device__ __forceinline__ void ldm_x4(uint32_t* r, uint32_t addr) {
    asm volatile("ldmatrix.sync.aligned.m8n8.x4.shared.b16 {%0,%1,%2,%3}, [%4];"
                 : "=r"(r[0]), "=r"(r[1]), "=r"(r[2]), "=r"(r[3]) : "r"(addr));
}
__device__ __forceinline__ void mma_f16(float* c, const uint32_t* a,
                                        uint32_t b0, uint32_t b1) {
    asm volatile(
        "mma.sync.aligned.m16n8k16.row.col.f32.f16.f16.f32 "
        "{%0,%1,%2,%3}, {%4,%5,%6,%7}, {%8,%9}, {%0,%1,%2,%3};"
        : "+f"(c[0]), "+f"(c[1]), "+f"(c[2]), "+f"(c[3])
        : "r"(a[0]), "r"(a[1]), "r"(a[2]), "r"(a[3]), "r"(b0), "r"(b1));
}
__device__ __forceinline__ void bar_pair(int id) {
    asm volatile("bar.sync %0, 64;" :: "r"(id) : "memory");
}

// ---------------- prep (unchanged) ----------------
__global__ void prep_kernel(const float* __restrict__ x,
                            const float* __restrict__ w) {
    const int stride = gridDim.x * blockDim.x;
    const int tid = blockIdx.x * blockDim.x + threadIdx.x;

    for (int i = tid; i < B_ * CIN_ * P_; i += stride) {
        int s = i % P_;
        int c = (i / P_) % CIN_;
        int b = i / (P_ * CIN_);
        g_xT[(b * P_ + s) * CIN_ + c] = x[i];
    }

    for (int i = tid; i < K_ * 8 * 2 * 32 * 4; i += stride) {
        int uu = i & 3;
        int ln = (i >> 2) & 31;
        int kp = (i >> 7) & 1;
        int jg = (i >> 8) & 7;
        int kt = i >> 11;
        int ks  = kp * 2 + (uu >> 1);
        int reg = uu & 1;
        int n = jg * 8 + (ln >> 2);
        int c = ks * 16 + (ln & 3) * 2 + reg * 8;
        float v0 = w[(n * CIN_ + c) * K_ + kt];
        float v1 = w[(n * CIN_ + c + 1) * K_ + kt];
        __half h0 = __float2half_rn(v0);
        __half h1 = __float2half_rn(v1);
        g_wF[i] = ((uint32_t)__half_as_ushort(h1) << 16) |
                  (uint32_t)__half_as_ushort(h0);
    }
}

// ---------------- main ----------------
__global__ __launch_bounds__(THREADS, 3)
void deform_hmma_kernel(const float* __restrict__ offset,
                        const float* __restrict__ bias,
                        float* __restrict__ out) {
    extern __shared__ __align__(1024) char smem[];
    const uint32_t sb = smem_u32(smem);

    const int tid  = threadIdx.x;
    const int lane = tid & 31;
    const int warp = tid >> 5;               // 8 warps
    const int blk  = blockIdx.x;
    const int b    = blk >> 7;
    const int p0   = (blk & 127) * MTILE;

    const float* offB = offset + (size_t)b * 3 * K_ * P_;
    const char*  xb   = reinterpret_cast<const char*>(g_xT + (size_t)b * P_ * CIN_);

    // sampling role: half-warp = one point; 4 passes x 2 points per tap
    const int hp   = lane >> 4;
    const int c4   = lane & 15;
    const int pl_base = warp * 8;
    const char* base2 = xb + (uint32_t)(c4 << 4);

    int   pg[4];
    float odf[4], ohf[4], owf[4];
    uint32_t wAoff[4];
#pragma unroll
    for (int i = 0; i < 4; i++) {
        const int pl = pl_base + 2 * i + hp;
        const int p  = p0 + pl;
        pg[i]  = p;
        odf[i] = (float)((p >> 10) - 1);
        ohf[i] = (float)(((p >> 5) & 31) - 1);
        owf[i] = (float)((p & 31) - 1);
        wAoff[i] = (uint32_t)(pl * 128 + ((c4 * 8) ^ ((pl & 7) << 4)));
    }

    // mma role
    const int mt = warp >> 1, nt = warp & 1;
    const int rowA = mt * 16 + (lane & 15);
    const uint32_t aBaseOff = (uint32_t)(rowA * 128);
    const uint32_t aXor = (uint32_t)((rowA & 7) << 4);
    const uint32_t aKh  = (uint32_t)((lane >> 4) << 4);

    float acc[4][4];
#pragma unroll
    for (int j = 0; j < 4; j++)
#pragma unroll
        for (int q = 0; q < 4; q++) acc[j][q] = 0.f;

    const uint4* gF = reinterpret_cast<const uint4*>(g_wF);

#pragma unroll 1
    for (int kt = 0; kt < K_; kt++) {
        const int buf = kt & 1;
        char* AP = smem + buf * ABUF;
        const uint32_t AB = sb + buf * ABUF;

        const float kdf = (float)(kt / 9);
        const float khf = (float)((kt / 3) % 3);
        const float kwf = (float)(kt % 3);
        const float* offk = offB + 3 * kt * P_;

#pragma unroll
        for (int i = 0; i < 4; i++) {
            const int p = pg[i];

            float zd = odf[i] + kdf + __ldg(offk + p);
            float zh = ohf[i] + khf + __ldg(offk + P_ + p);
            float zw = owf[i] + kwf + __ldg(offk + 2 * P_ + p);

            float fd = floorf(zd); int d0 = (int)fd; float rd = zd - fd;
            float fh = floorf(zh); int h0 = (int)fh; float rh = zh - fh;
            float fw = floorf(zw); int w0 = (int)fw; float rw = zw - fw;

            float wd0 = ((unsigned)d0       < (unsigned)D_) ? 1.f - rd : 0.f;
            float wd1 = ((unsigned)(d0 + 1) < (unsigned)D_) ? rd       : 0.f;
            float wh0 = ((unsigned)h0       < (unsigned)H_) ? 1.f - rh : 0.f;
            float wh1 = ((unsigned)(h0 + 1) < (unsigned)H_) ? rh       : 0.f;
            float ww0 = ((unsigned)w0       < (unsigned)W_) ? 1.f - rw : 0.f;
            float ww1 = ((unsigned)(w0 + 1) < (unsigned)W_) ? rw       : 0.f;

            const int s0 = d0 * 1024 + h0 * 32 + w0;
            const float w00 = wd0 * wh0, w01 = wd0 * wh1;
            const float w10 = wd1 * wh0, w11 = wd1 * wh1;

            float ax, ay, az, aw;
            // chunk 1: d0 plane (corners 0-3) — 16 gather regs live
            {
                uint32_t i0 = ((uint32_t)s0        & 8191u) << 8;
                uint32_t i1 = ((uint32_t)(s0 + 1)  & 8191u) << 8;
                uint32_t i2 = ((uint32_t)(s0 + 32) & 8191u) << 8;
                uint32_t i3 = ((uint32_t)(s0 + 33) & 8191u) << 8;
                float4 v0 = __ldg(reinterpret_cast<const float4*>(base2 + i0));
                float4 v1 = __ldg(reinterpret_cast<const float4*>(base2 + i1));
                float4 v2 = __ldg(reinterpret_cast<const float4*>(base2 + i2));
                float4 v3 = __ldg(reinterpret_cast<const float4*>(base2 + i3));
                const float g0 = w00 * ww0, g1 = w00 * ww1;
                const float g2 = w01 * ww0, g3 = w01 * ww1;
                ax = g0 * v0.x + g1 * v1.x + g2 * v2.x + g3 * v3.x;
                ay = g0 * v0.y + g1 * v1.y + g2 * v2.y + g3 * v3.y;
                az = g0 * v0.z + g1 * v1.z + g2 * v2.z + g3 * v3.z;
                aw = g0 * v0.w + g1 * v1.w + g2 * v2.w + g3 * v3.w;
            }
            // chunk 2: d1 plane (corners 4-7)
            {
                const int s1 = s0 + 1024;
                uint32_t i0 = ((uint32_t)s1        & 8191u) << 8;
                uint32_t i1 = ((uint32_t)(s1 + 1)  & 8191u) << 8;
                uint32_t i2 = ((uint32_t)(s1 + 32) & 8191u) << 8;
                uint32_t i3 = ((uint32_t)(s1 + 33) & 8191u) << 8;
                float4 v0 = __ldg(reinterpret_cast<const float4*>(base2 + i0));
                float4 v1 = __ldg(reinterpret_cast<const float4*>(base2 + i1));
                float4 v2 = __ldg(reinterpret_cast<const float4*>(base2 + i2));
                float4 v3 = __ldg(reinterpret_cast<const float4*>(base2 + i3));
                const float g4 = w10 * ww0, g5 = w10 * ww1;
                const float g6 = w11 * ww0, g7 = w11 * ww1;
                ax += g4 * v0.x + g5 * v1.x + g6 * v2.x + g7 * v3.x;
                ay += g4 * v0.y + g5 * v1.y + g6 * v2.y + g7 * v3.y;
                az += g4 * v0.z + g5 * v1.z + g6 * v2.z + g7 * v3.z;
                aw += g4 * v0.w + g5 * v1.w + g6 * v2.w + g7 * v3.w;
            }

            uint32_t h01 = f16x2(ay, ax);       // {lo=ch+0, hi=ch+1}
            uint32_t h23 = f16x2(aw, az);
            *reinterpret_cast<uint2*>(AP + wAoff[i]) = make_uint2(h01, h23);
        }

        bar_pair(mt + 1);

        // ---- MMA: 2 k-step pairs, single term ----
        const size_t ktBase = (size_t)kt * 512 + (size_t)(nt * 4) * 64 + lane;
#pragma unroll
        for (int kp = 0; kp < 2; kp++) {
            uint32_t ah0[4], ah1[4];
            const uint32_t ao0 = aBaseOff + (((uint32_t)(kp * 64) + aKh) ^ aXor);
            const uint32_t ao1 = aBaseOff + (((uint32_t)(kp * 64 + 32) + aKh) ^ aXor);
            ldm_x4(ah0, AB + ao0);
            ldm_x4(ah1, AB + ao1);
#pragma unroll
            for (int j = 0; j < 4; j++) {
                uint4 q = __ldg(gF + ktBase + (size_t)(j * 64 + kp * 32));
                mma_f16(acc[j], ah0, q.x, q.y);
                mma_f16(acc[j], ah1, q.z, q.w);
            }
        }
    }

    // ---- epilogue ----
    const int m = lane >> 2;
    const int p = p0 + mt * 16 + m;
#pragma unroll
    for (int j = 0; j < 4; j++) {
        const int n = nt * 32 + j * 8 + 2 * (lane & 3);
        const float bv0 = __ldg(&bias[n]);
        const float bv1 = __ldg(&bias[n + 1]);
        float* o0 = out + ((size_t)(b * COUT_ + n)) * P_ + p;
        o0[0]      = acc[j][0] + bv0;
        o0[P_]     = acc[j][1] + bv1;
        o0[8]      = acc[j][2] + bv0;
        o0[P_ + 8] = acc[j][3] + bv1;
    }
}

extern "C" void kernel_launch(void* const* d_in, const int* in_sizes, int n_in,
                              void* d_out, int out_size) {
    const float* x      = (const float*)d_in[0];
    const float* offset = (const float*)d_in[1];
    const float* weight = (const float*)d_in[2];
    const float* bias   = (const float*)d_in[3];
    float* out = (float*)d_out;

    cudaFuncSetAttribute(deform_hmma_kernel,
                         cudaFuncAttributeMaxDynamicSharedMemorySize, SM_TOTAL);
    prep_kernel<<<256, 256>>>(x, weight);
    deform_hmma_kernel<<<NBLK, THREADS, SM_TOTAL>>>(offset, bias, out);
}